// round 1
// baseline (speedup 1.0000x reference)
#include <cuda_runtime.h>
#include <cuda_bf16.h>
#include <math.h>

// Problem constants
#define B_ 4
#define T_ 2048
#define D_ 1024
#define H_ 16
#define DK_ 64
#define M_ (B_ * T_)   // 8192 rows for projections

// Scratch (device globals; allocation-free)
__device__ float g_q[B_ * T_ * D_];
__device__ float g_k[B_ * T_ * D_];
__device__ float g_v[B_ * T_ * D_];
__device__ float g_ctx[B_ * T_ * D_];

// ---------------------------------------------------------------------------
// GEMM: C[M,N] = A[M,K] @ W[N,K]^T + bias[N]   (fp32 SIMT, 64x64x16 tiles)
// ---------------------------------------------------------------------------
#define GBM 64
#define GBN 64
#define GBK 16

__global__ __launch_bounds__(256) void gemm_bias_kernel(
    const float* __restrict__ A, const float* __restrict__ W,
    const float* __restrict__ bias, float* __restrict__ C,
    int M, int N, int K)
{
    __shared__ float As[GBK][GBM + 1];
    __shared__ float Ws[GBK][GBN + 1];

    const int t = threadIdx.x;
    const int bm = blockIdx.y * GBM;
    const int bn = blockIdx.x * GBN;
    const int tm = (t / 16) * 4;
    const int tn = (t % 16) * 4;

    // loader mapping: 64 rows x 16 k, one float4 per thread
    const int lr = t / 4;          // row 0..63
    const int lc = (t % 4) * 4;    // k 0..12

    float acc[4][4] = {};

    for (int k0 = 0; k0 < K; k0 += GBK) {
        float4 av = *(const float4*)&A[(size_t)(bm + lr) * K + k0 + lc];
        float4 wv = *(const float4*)&W[(size_t)(bn + lr) * K + k0 + lc];
        As[lc + 0][lr] = av.x; As[lc + 1][lr] = av.y;
        As[lc + 2][lr] = av.z; As[lc + 3][lr] = av.w;
        Ws[lc + 0][lr] = wv.x; Ws[lc + 1][lr] = wv.y;
        Ws[lc + 2][lr] = wv.z; Ws[lc + 3][lr] = wv.w;
        __syncthreads();

        #pragma unroll
        for (int k = 0; k < GBK; k++) {
            float a[4], w[4];
            #pragma unroll
            for (int i = 0; i < 4; i++) a[i] = As[k][tm + i];
            #pragma unroll
            for (int j = 0; j < 4; j++) w[j] = Ws[k][tn + j];
            #pragma unroll
            for (int i = 0; i < 4; i++)
                #pragma unroll
                for (int j = 0; j < 4; j++)
                    acc[i][j] = fmaf(a[i], w[j], acc[i][j]);
        }
        __syncthreads();
    }

    #pragma unroll
    for (int i = 0; i < 4; i++) {
        #pragma unroll
        for (int j = 0; j < 4; j++) {
            C[(size_t)(bm + tm + i) * N + bn + tn + j] = acc[i][j] + bias[bn + tn + j];
        }
    }
}

// ---------------------------------------------------------------------------
// RoPE on q and k in place. cos/sin: [T, DK]. Layout [B,T,H,DK].
// One thread per (b,t,h, d in 0..31) pair.
// ---------------------------------------------------------------------------
__global__ __launch_bounds__(256) void rope_kernel(
    float* __restrict__ q, float* __restrict__ k,
    const float* __restrict__ cosp, const float* __restrict__ sinp)
{
    int idx = blockIdx.x * blockDim.x + threadIdx.x;  // up to B*T*H*32
    int d = idx & 31;
    int tt = (idx >> 9) & (T_ - 1);
    size_t base = (size_t)(idx >> 5) * DK_;  // ((b*T+t)*H + h) * DK

    float c1 = cosp[tt * DK_ + d];
    float s1 = sinp[tt * DK_ + d];
    float c2 = cosp[tt * DK_ + d + 32];
    float s2 = sinp[tt * DK_ + d + 32];

    float x1 = q[base + d], x2 = q[base + d + 32];
    q[base + d]      = x1 * c1 - x2 * s1;
    q[base + d + 32] = x2 * c2 + x1 * s2;

    float y1 = k[base + d], y2 = k[base + d + 32];
    k[base + d]      = y1 * c1 - y2 * s1;
    k[base + d + 32] = y2 * c2 + y1 * s2;
}

// ---------------------------------------------------------------------------
// Flash attention. Block = (qtile=64 rows, h, b). 256 threads.
// Shared: Qs/Ks/Vs/Ps each [64][65] fp32 = 66,560 B dynamic.
// Per-thread 4x4 micro-tiles for S and for PV accumulation.
// ---------------------------------------------------------------------------
#define FPAD 65

__global__ __launch_bounds__(256) void flash_attn_kernel(
    const float* __restrict__ Q, const float* __restrict__ K,
    const float* __restrict__ V, const unsigned char* __restrict__ mask,
    float* __restrict__ O)
{
    extern __shared__ float sm[];
    float (*Qs)[FPAD] = (float(*)[FPAD])(sm);
    float (*Ks)[FPAD] = (float(*)[FPAD])(sm + 64 * FPAD);
    float (*Vs)[FPAD] = (float(*)[FPAD])(sm + 2 * 64 * FPAD);
    float (*Ps)[FPAD] = (float(*)[FPAD])(sm + 3 * 64 * FPAD);

    const int t = threadIdx.x;
    const int qt = blockIdx.x;
    const int h  = blockIdx.y;
    const int b  = blockIdx.z;

    const int tm = (t / 16) * 4;   // row group (0..60)
    const int tn = (t % 16) * 4;   // col group (0..60)

    const int lr = t / 4;          // loader row 0..63
    const int lc = (t % 4) * 16;   // loader dim offset

    const float scale = 0.125f;    // 1/sqrt(64)

    // Load + scale Q tile
    {
        const float* qp = Q + ((size_t)(b * T_ + qt * 64 + lr) * D_) + h * DK_ + lc;
        #pragma unroll
        for (int ii = 0; ii < 4; ii++) {
            float4 v4 = *(const float4*)(qp + ii * 4);
            Qs[lr][lc + ii * 4 + 0] = v4.x * scale;
            Qs[lr][lc + ii * 4 + 1] = v4.y * scale;
            Qs[lr][lc + ii * 4 + 2] = v4.z * scale;
            Qs[lr][lc + ii * 4 + 3] = v4.w * scale;
        }
    }

    float m[4], l[4], acc[4][4];
    #pragma unroll
    for (int i = 0; i < 4; i++) { m[i] = -1e30f; l[i] = 0.0f; }
    #pragma unroll
    for (int i = 0; i < 4; i++)
        #pragma unroll
        for (int j = 0; j < 4; j++) acc[i][j] = 0.0f;

    const unsigned char* mrow = mask + (size_t)(b * T_ + qt * 64) * T_;

    for (int kt = 0; kt < T_ / 64; kt++) {
        // Load K, V tiles
        {
            const float* kp = K + ((size_t)(b * T_ + kt * 64 + lr) * D_) + h * DK_ + lc;
            const float* vp = V + ((size_t)(b * T_ + kt * 64 + lr) * D_) + h * DK_ + lc;
            #pragma unroll
            for (int ii = 0; ii < 4; ii++) {
                float4 kv = *(const float4*)(kp + ii * 4);
                Ks[lr][lc + ii * 4 + 0] = kv.x;
                Ks[lr][lc + ii * 4 + 1] = kv.y;
                Ks[lr][lc + ii * 4 + 2] = kv.z;
                Ks[lr][lc + ii * 4 + 3] = kv.w;
                float4 vv = *(const float4*)(vp + ii * 4);
                Vs[lr][lc + ii * 4 + 0] = vv.x;
                Vs[lr][lc + ii * 4 + 1] = vv.y;
                Vs[lr][lc + ii * 4 + 2] = vv.z;
                Vs[lr][lc + ii * 4 + 3] = vv.w;
            }
        }
        __syncthreads();

        // S = Q K^T (4x4 per thread)
        float s[4][4] = {};
        #pragma unroll
        for (int d = 0; d < DK_; d++) {
            float a[4], bb[4];
            #pragma unroll
            for (int i = 0; i < 4; i++) a[i] = Qs[tm + i][d];
            #pragma unroll
            for (int j = 0; j < 4; j++) bb[j] = Ks[tn + j][d];
            #pragma unroll
            for (int i = 0; i < 4; i++)
                #pragma unroll
                for (int j = 0; j < 4; j++)
                    s[i][j] = fmaf(a[i], bb[j], s[i][j]);
        }

        // Mask
        #pragma unroll
        for (int i = 0; i < 4; i++) {
            const unsigned char* mp = mrow + (size_t)(tm + i) * T_ + kt * 64 + tn;
            #pragma unroll
            for (int j = 0; j < 4; j++)
                if (mp[j]) s[i][j] = -1e30f;
        }

        // Online softmax update
        float mnew[4], ef[4], rs[4];
        #pragma unroll
        for (int i = 0; i < 4; i++) {
            float rmax = fmaxf(fmaxf(s[i][0], s[i][1]), fmaxf(s[i][2], s[i][3]));
            #pragma unroll
            for (int off = 1; off < 16; off <<= 1)
                rmax = fmaxf(rmax, __shfl_xor_sync(0xffffffffu, rmax, off));
            mnew[i] = fmaxf(m[i], rmax);
            ef[i] = __expf(m[i] - mnew[i]);
            m[i] = mnew[i];
        }
        #pragma unroll
        for (int i = 0; i < 4; i++) {
            float psum = 0.0f;
            #pragma unroll
            for (int j = 0; j < 4; j++) {
                float p = __expf(s[i][j] - mnew[i]);
                Ps[tm + i][tn + j] = p;
                psum += p;
            }
            #pragma unroll
            for (int off = 1; off < 16; off <<= 1)
                psum += __shfl_xor_sync(0xffffffffu, psum, off);
            rs[i] = psum;
        }
        #pragma unroll
        for (int i = 0; i < 4; i++) {
            l[i] = l[i] * ef[i] + rs[i];
            #pragma unroll
            for (int j = 0; j < 4; j++) acc[i][j] *= ef[i];
        }
        __syncthreads();

        // acc += P @ V
        #pragma unroll
        for (int c = 0; c < 64; c++) {
            float pr[4], vv[4];
            #pragma unroll
            for (int i = 0; i < 4; i++) pr[i] = Ps[tm + i][c];
            #pragma unroll
            for (int j = 0; j < 4; j++) vv[j] = Vs[c][tn + j];
            #pragma unroll
            for (int i = 0; i < 4; i++)
                #pragma unroll
                for (int j = 0; j < 4; j++)
                    acc[i][j] = fmaf(pr[i], vv[j], acc[i][j]);
        }
        __syncthreads();
    }

    // Write out (divide by l)
    #pragma unroll
    for (int i = 0; i < 4; i++) {
        float inv = 1.0f / l[i];
        #pragma unroll
        for (int j = 0; j < 4; j++) {
            O[((size_t)(b * T_ + qt * 64 + tm + i) * D_) + h * DK_ + tn + j] = acc[i][j] * inv;
        }
    }
}

// ---------------------------------------------------------------------------
// Launch
// ---------------------------------------------------------------------------
extern "C" void kernel_launch(void* const* d_in, const int* in_sizes, int n_in,
                              void* d_out, int out_size)
{
    const float* query = (const float*)d_in[0];
    const float* key   = (const float*)d_in[1];
    const float* value = (const float*)d_in[2];
    const float* cosp  = (const float*)d_in[3];
    const float* sinp  = (const float*)d_in[4];
    const unsigned char* mask = (const unsigned char*)d_in[5];
    const float* Wq = (const float*)d_in[6];
    const float* bq = (const float*)d_in[7];
    const float* Wk = (const float*)d_in[8];
    const float* bk = (const float*)d_in[9];
    const float* Wv = (const float*)d_in[10];
    const float* bv = (const float*)d_in[11];
    const float* Wo = (const float*)d_in[12];
    const float* bo = (const float*)d_in[13];

    float *q, *k, *v, *ctx;
    cudaGetSymbolAddress((void**)&q,   g_q);
    cudaGetSymbolAddress((void**)&k,   g_k);
    cudaGetSymbolAddress((void**)&v,   g_v);
    cudaGetSymbolAddress((void**)&ctx, g_ctx);

    dim3 ggrid(D_ / GBN, M_ / GBM);  // (16, 128)

    gemm_bias_kernel<<<ggrid, 256>>>(query, Wq, bq, q,   M_, D_, D_);
    gemm_bias_kernel<<<ggrid, 256>>>(key,   Wk, bk, k,   M_, D_, D_);
    gemm_bias_kernel<<<ggrid, 256>>>(value, Wv, bv, v,   M_, D_, D_);

    int rope_threads = B_ * T_ * H_ * 32;
    rope_kernel<<<rope_threads / 256, 256>>>(q, k, cosp, sinp);

    int smem = 4 * 64 * FPAD * sizeof(float);  // 66,560 B
    cudaFuncSetAttribute(flash_attn_kernel,
                         cudaFuncAttributeMaxDynamicSharedMemorySize, smem);
    flash_attn_kernel<<<dim3(T_ / 64, H_, B_), 256, smem>>>(q, k, v, mask, ctx);

    gemm_bias_kernel<<<ggrid, 256>>>(ctx, Wo, bo, (float*)d_out, M_, D_, D_);
}

// round 2
// speedup vs baseline: 3.3625x; 3.3625x over previous
#include <cuda_runtime.h>
#include <cuda_bf16.h>
#include <math.h>

// Problem constants
#define B_ 4
#define T_ 2048
#define D_ 1024
#define H_ 16
#define DK_ 64
#define M_ (B_ * T_)   // 8192 rows for projections

// Scratch (device globals; allocation-free)
__device__ float g_q[B_ * T_ * D_];
__device__ float g_k[B_ * T_ * D_];
__device__ float g_v[B_ * T_ * D_];
__device__ float g_ctx[B_ * T_ * D_];

// ---------------------------------------------------------------------------
// Helpers
// ---------------------------------------------------------------------------
__device__ __forceinline__ unsigned f2tf32(float f) {
    unsigned u;
    asm("cvt.rna.tf32.f32 %0, %1;" : "=r"(u) : "f"(f));
    return u;
}

__device__ __forceinline__ void mma_tf32(float* d, const unsigned* a,
                                         const unsigned* b) {
    asm volatile(
        "mma.sync.aligned.m16n8k8.row.col.f32.tf32.tf32.f32 "
        "{%0,%1,%2,%3},{%4,%5,%6,%7},{%8,%9},{%0,%1,%2,%3};\n"
        : "+f"(d[0]), "+f"(d[1]), "+f"(d[2]), "+f"(d[3])
        : "r"(a[0]), "r"(a[1]), "r"(a[2]), "r"(a[3]),
          "r"(b[0]), "r"(b[1]));
}

// ---------------------------------------------------------------------------
// GEMM: C[M,N] = A[M,K] @ W[N,K]^T + bias[N]  (tf32 tensor core)
// Block tile 128x128, K-chunk 32, 256 threads = 8 warps (2m x 4n),
// warp tile 64x32 (4 m16-tiles x 4 n8-tiles).
// ---------------------------------------------------------------------------
#define GBM 128
#define GBN 128
#define GBK 32
#define GST 36  // smem row stride (floats); 36 mod 32 = 4 -> conflict-free

__global__ __launch_bounds__(256) void gemm_tc_kernel(
    const float* __restrict__ A, const float* __restrict__ W,
    const float* __restrict__ bias, float* __restrict__ C,
    int M, int N, int K)
{
    __shared__ float As[GBM * GST];
    __shared__ float Bs[GBN * GST];

    const int t   = threadIdx.x;
    const int bm  = blockIdx.y * GBM;
    const int bn  = blockIdx.x * GBN;
    const int w   = t >> 5;
    const int ln  = t & 31;
    const int gid = ln >> 2;
    const int tig = ln & 3;
    const int wm  = (w >> 2) * 64;   // warp m origin (0 or 64)
    const int wn  = (w & 3) * 32;    // warp n origin

    float acc[4][4][4];
    #pragma unroll
    for (int i = 0; i < 4; i++)
        #pragma unroll
        for (int j = 0; j < 4; j++)
            #pragma unroll
            for (int r = 0; r < 4; r++) acc[i][j][r] = 0.0f;

    for (int k0 = 0; k0 < K; k0 += GBK) {
        // Load A and B chunks: 128x32 each = 1024 float4; 4 per thread.
        #pragma unroll
        for (int i = 0; i < 4; i++) {
            int idx = t + i * 256;
            int row = idx >> 3;
            int c4  = (idx & 7) * 4;
            float4 av = *(const float4*)&A[(size_t)(bm + row) * K + k0 + c4];
            float* as = &As[row * GST + c4];
            as[0] = __uint_as_float(f2tf32(av.x));
            as[1] = __uint_as_float(f2tf32(av.y));
            as[2] = __uint_as_float(f2tf32(av.z));
            as[3] = __uint_as_float(f2tf32(av.w));
            float4 wv = *(const float4*)&W[(size_t)(bn + row) * K + k0 + c4];
            float* bs = &Bs[row * GST + c4];
            bs[0] = __uint_as_float(f2tf32(wv.x));
            bs[1] = __uint_as_float(f2tf32(wv.y));
            bs[2] = __uint_as_float(f2tf32(wv.z));
            bs[3] = __uint_as_float(f2tf32(wv.w));
        }
        __syncthreads();

        #pragma unroll
        for (int ks = 0; ks < 4; ks++) {
            const int kk = ks * 8;
            unsigned af[4][4], bf[4][2];
            #pragma unroll
            for (int mt = 0; mt < 4; mt++) {
                const float* p = &As[(wm + mt * 16 + gid) * GST + kk + tig];
                af[mt][0] = __float_as_uint(p[0]);
                af[mt][1] = __float_as_uint(p[8 * GST]);
                af[mt][2] = __float_as_uint(p[4]);
                af[mt][3] = __float_as_uint(p[8 * GST + 4]);
            }
            #pragma unroll
            for (int nt = 0; nt < 4; nt++) {
                const float* p = &Bs[(wn + nt * 8 + gid) * GST + kk + tig];
                bf[nt][0] = __float_as_uint(p[0]);
                bf[nt][1] = __float_as_uint(p[4]);
            }
            #pragma unroll
            for (int mt = 0; mt < 4; mt++)
                #pragma unroll
                for (int nt = 0; nt < 4; nt++)
                    mma_tf32(acc[mt][nt], af[mt], bf[nt]);
        }
        __syncthreads();
    }

    // Epilogue
    #pragma unroll
    for (int mt = 0; mt < 4; mt++) {
        #pragma unroll
        for (int nt = 0; nt < 4; nt++) {
            int col = bn + wn + nt * 8 + tig * 2;
            float b0 = bias[col], b1 = bias[col + 1];
            int r0 = bm + wm + mt * 16 + gid;
            float2 v0 = make_float2(acc[mt][nt][0] + b0, acc[mt][nt][1] + b1);
            float2 v1 = make_float2(acc[mt][nt][2] + b0, acc[mt][nt][3] + b1);
            *(float2*)&C[(size_t)r0 * N + col]       = v0;
            *(float2*)&C[(size_t)(r0 + 8) * N + col] = v1;
        }
    }
}

// ---------------------------------------------------------------------------
// RoPE on q and k in place. cos/sin: [T, DK]. Layout [B,T,H,DK].
// ---------------------------------------------------------------------------
__global__ __launch_bounds__(256) void rope_kernel(
    float* __restrict__ q, float* __restrict__ k,
    const float* __restrict__ cosp, const float* __restrict__ sinp)
{
    int idx = blockIdx.x * blockDim.x + threadIdx.x;
    int d = idx & 31;
    int tt = (idx >> 9) & (T_ - 1);
    size_t base = (size_t)(idx >> 5) * DK_;

    float c1 = cosp[tt * DK_ + d];
    float s1 = sinp[tt * DK_ + d];
    float c2 = cosp[tt * DK_ + d + 32];
    float s2 = sinp[tt * DK_ + d + 32];

    float x1 = q[base + d], x2 = q[base + d + 32];
    q[base + d]      = x1 * c1 - x2 * s1;
    q[base + d + 32] = x2 * c2 + x1 * s2;

    float y1 = k[base + d], y2 = k[base + d + 32];
    k[base + d]      = y1 * c1 - y2 * s1;
    k[base + d + 32] = y2 * c2 + y1 * s2;
}

// ---------------------------------------------------------------------------
// Flash attention, tensor-core version.
// Block: 128 q-rows for one (b,h); 8 warps x 16 rows. Key tiles of 64.
// S = Q K^T and O += P V both via tf32 mma.
// ---------------------------------------------------------------------------
#define AST 68  // smem stride; 68 mod 32 = 4 -> conflict-free

__global__ __launch_bounds__(256) void flash_tc_kernel(
    const float* __restrict__ Q, const float* __restrict__ K,
    const float* __restrict__ V, const unsigned char* __restrict__ mask,
    float* __restrict__ O)
{
    extern __shared__ float sm[];
    float* Qs = sm;                    // [128][AST]
    float* Ks = Qs + 128 * AST;        // [64][AST]
    float* Vs = Ks + 64 * AST;         // [64][AST]
    float* Ps = Vs + 64 * AST;         // [128][AST]

    const int t   = threadIdx.x;
    const int qt  = blockIdx.x;        // 16 q-tiles of 128
    const int h   = blockIdx.y;
    const int b   = blockIdx.z;
    const int w   = t >> 5;
    const int ln  = t & 31;
    const int gid = ln >> 2;
    const int tig = ln & 3;
    const int wr  = w * 16;            // warp's q-row origin within tile

    const float scale = 0.125f;

    // Load Q tile (128 x 64), scale, convert tf32. 2048 float4 / 256 thr = 8.
    #pragma unroll
    for (int i = 0; i < 8; i++) {
        int idx = t + i * 256;
        int row = idx >> 4;
        int c4  = (idx & 15) * 4;
        const float* qp = Q + ((size_t)(b * T_ + qt * 128 + row) * D_) + h * DK_ + c4;
        float4 v4 = *(const float4*)qp;
        float* qs = &Qs[row * AST + c4];
        qs[0] = __uint_as_float(f2tf32(v4.x * scale));
        qs[1] = __uint_as_float(f2tf32(v4.y * scale));
        qs[2] = __uint_as_float(f2tf32(v4.z * scale));
        qs[3] = __uint_as_float(f2tf32(v4.w * scale));
    }

    float o[8][4];
    #pragma unroll
    for (int nt = 0; nt < 8; nt++)
        #pragma unroll
        for (int r = 0; r < 4; r++) o[nt][r] = 0.0f;
    float m0 = -1e30f, m1 = -1e30f, l0 = 0.0f, l1 = 0.0f;

    const size_t mbase = (size_t)(b * T_ + qt * 128) * T_;

    for (int kt = 0; kt < T_ / 64; kt++) {
        // Load K,V tiles (64x64 each): 1024 float4 each / 256 thr = 4 each.
        #pragma unroll
        for (int i = 0; i < 4; i++) {
            int idx = t + i * 256;
            int row = idx >> 4;
            int c4  = (idx & 15) * 4;
            size_t goff = ((size_t)(b * T_ + kt * 64 + row) * D_) + h * DK_ + c4;
            float4 kv = *(const float4*)(K + goff);
            float* ks = &Ks[row * AST + c4];
            ks[0] = __uint_as_float(f2tf32(kv.x));
            ks[1] = __uint_as_float(f2tf32(kv.y));
            ks[2] = __uint_as_float(f2tf32(kv.z));
            ks[3] = __uint_as_float(f2tf32(kv.w));
            float4 vv = *(const float4*)(V + goff);
            float* vs = &Vs[row * AST + c4];
            vs[0] = __uint_as_float(f2tf32(vv.x));
            vs[1] = __uint_as_float(f2tf32(vv.y));
            vs[2] = __uint_as_float(f2tf32(vv.z));
            vs[3] = __uint_as_float(f2tf32(vv.w));
        }
        __syncthreads();

        // S = Qs @ Ks^T : warp computes 16 rows x 64 keys = 8 n8-tiles
        float s[8][4];
        #pragma unroll
        for (int nt = 0; nt < 8; nt++)
            #pragma unroll
            for (int r = 0; r < 4; r++) s[nt][r] = 0.0f;

        #pragma unroll
        for (int ks = 0; ks < 8; ks++) {
            const int kk = ks * 8;
            unsigned af[4];
            const float* ap = &Qs[(wr + gid) * AST + kk + tig];
            af[0] = __float_as_uint(ap[0]);
            af[1] = __float_as_uint(ap[8 * AST]);
            af[2] = __float_as_uint(ap[4]);
            af[3] = __float_as_uint(ap[8 * AST + 4]);
            #pragma unroll
            for (int nt = 0; nt < 8; nt++) {
                unsigned bf[2];
                const float* bp = &Ks[(nt * 8 + gid) * AST + kk + tig];
                bf[0] = __float_as_uint(bp[0]);
                bf[1] = __float_as_uint(bp[4]);
                mma_tf32(s[nt], af, bf);
            }
        }

        // Mask
        {
            const unsigned char* mr0 = (const unsigned char*)mask + mbase
                + (size_t)(wr + gid) * T_ + kt * 64;
            const unsigned char* mr1 = mr0 + (size_t)8 * T_;
            #pragma unroll
            for (int nt = 0; nt < 8; nt++) {
                int col = nt * 8 + tig * 2;
                uchar2 u0 = *(const uchar2*)(mr0 + col);
                uchar2 u1 = *(const uchar2*)(mr1 + col);
                if (u0.x) s[nt][0] = -1e30f;
                if (u0.y) s[nt][1] = -1e30f;
                if (u1.x) s[nt][2] = -1e30f;
                if (u1.y) s[nt][3] = -1e30f;
            }
        }

        // Online softmax. Rows: r0 = wr+gid, r1 = wr+gid+8; cols spread over
        // 8 nt-tiles x 2, plus the 4 lanes of the quad (shfl over tig).
        float rmax0 = -1e30f, rmax1 = -1e30f;
        #pragma unroll
        for (int nt = 0; nt < 8; nt++) {
            rmax0 = fmaxf(rmax0, fmaxf(s[nt][0], s[nt][1]));
            rmax1 = fmaxf(rmax1, fmaxf(s[nt][2], s[nt][3]));
        }
        rmax0 = fmaxf(rmax0, __shfl_xor_sync(0xffffffffu, rmax0, 1));
        rmax0 = fmaxf(rmax0, __shfl_xor_sync(0xffffffffu, rmax0, 2));
        rmax1 = fmaxf(rmax1, __shfl_xor_sync(0xffffffffu, rmax1, 1));
        rmax1 = fmaxf(rmax1, __shfl_xor_sync(0xffffffffu, rmax1, 2));

        float mn0 = fmaxf(m0, rmax0), mn1 = fmaxf(m1, rmax1);
        float ef0 = __expf(m0 - mn0), ef1 = __expf(m1 - mn1);
        m0 = mn0; m1 = mn1;

        float sum0 = 0.0f, sum1 = 0.0f;
        #pragma unroll
        for (int nt = 0; nt < 8; nt++) {
            float p0 = __expf(s[nt][0] - mn0);
            float p1 = __expf(s[nt][1] - mn0);
            float p2 = __expf(s[nt][2] - mn1);
            float p3 = __expf(s[nt][3] - mn1);
            sum0 += p0 + p1;
            sum1 += p2 + p3;
            int col = nt * 8 + tig * 2;
            float2 w0 = make_float2(__uint_as_float(f2tf32(p0)),
                                    __uint_as_float(f2tf32(p1)));
            float2 w1 = make_float2(__uint_as_float(f2tf32(p2)),
                                    __uint_as_float(f2tf32(p3)));
            *(float2*)&Ps[(wr + gid) * AST + col]     = w0;
            *(float2*)&Ps[(wr + gid + 8) * AST + col] = w1;
        }
        sum0 += __shfl_xor_sync(0xffffffffu, sum0, 1);
        sum0 += __shfl_xor_sync(0xffffffffu, sum0, 2);
        sum1 += __shfl_xor_sync(0xffffffffu, sum1, 1);
        sum1 += __shfl_xor_sync(0xffffffffu, sum1, 2);

        l0 = l0 * ef0 + sum0;
        l1 = l1 * ef1 + sum1;
        #pragma unroll
        for (int nt = 0; nt < 8; nt++) {
            o[nt][0] *= ef0; o[nt][1] *= ef0;
            o[nt][2] *= ef1; o[nt][3] *= ef1;
        }
        __syncwarp();

        // O += P @ V : A = Ps rows (warp's 16), B = Vs (64 keys x 64 dk)
        #pragma unroll
        for (int ks = 0; ks < 8; ks++) {
            const int kk = ks * 8;
            unsigned af[4];
            const float* ap = &Ps[(wr + gid) * AST + kk + tig];
            af[0] = __float_as_uint(ap[0]);
            af[1] = __float_as_uint(ap[8 * AST]);
            af[2] = __float_as_uint(ap[4]);
            af[3] = __float_as_uint(ap[8 * AST + 4]);
            #pragma unroll
            for (int nt = 0; nt < 8; nt++) {
                unsigned bf[2];
                const float* bp = &Vs[(kk + tig) * AST + nt * 8 + gid];
                bf[0] = __float_as_uint(bp[0]);
                bf[1] = __float_as_uint(bp[4 * AST]);
                mma_tf32(o[nt], af, bf);
            }
        }
        __syncthreads();
    }

    // Epilogue: divide by l, write.
    float inv0 = 1.0f / l0, inv1 = 1.0f / l1;
    size_t r0 = (size_t)(b * T_ + qt * 128 + wr + gid) * D_ + h * DK_;
    size_t r1 = r0 + (size_t)8 * D_;
    #pragma unroll
    for (int nt = 0; nt < 8; nt++) {
        int col = nt * 8 + tig * 2;
        *(float2*)&O[r0 + col] = make_float2(o[nt][0] * inv0, o[nt][1] * inv0);
        *(float2*)&O[r1 + col] = make_float2(o[nt][2] * inv1, o[nt][3] * inv1);
    }
}

// ---------------------------------------------------------------------------
// Launch
// ---------------------------------------------------------------------------
extern "C" void kernel_launch(void* const* d_in, const int* in_sizes, int n_in,
                              void* d_out, int out_size)
{
    const float* query = (const float*)d_in[0];
    const float* key   = (const float*)d_in[1];
    const float* value = (const float*)d_in[2];
    const float* cosp  = (const float*)d_in[3];
    const float* sinp  = (const float*)d_in[4];
    const unsigned char* mask = (const unsigned char*)d_in[5];
    const float* Wq = (const float*)d_in[6];
    const float* bq = (const float*)d_in[7];
    const float* Wk = (const float*)d_in[8];
    const float* bk = (const float*)d_in[9];
    const float* Wv = (const float*)d_in[10];
    const float* bv = (const float*)d_in[11];
    const float* Wo = (const float*)d_in[12];
    const float* bo = (const float*)d_in[13];

    float *q, *k, *v, *ctx;
    cudaGetSymbolAddress((void**)&q,   g_q);
    cudaGetSymbolAddress((void**)&k,   g_k);
    cudaGetSymbolAddress((void**)&v,   g_v);
    cudaGetSymbolAddress((void**)&ctx, g_ctx);

    dim3 ggrid(D_ / GBN, M_ / GBM);  // (8, 64)

    gemm_tc_kernel<<<ggrid, 256>>>(query, Wq, bq, q,   M_, D_, D_);
    gemm_tc_kernel<<<ggrid, 256>>>(key,   Wk, bk, k,   M_, D_, D_);
    gemm_tc_kernel<<<ggrid, 256>>>(value, Wv, bv, v,   M_, D_, D_);

    int rope_threads = B_ * T_ * H_ * 32;
    rope_kernel<<<rope_threads / 256, 256>>>(q, k, cosp, sinp);

    int smem = (128 + 64 + 64 + 128) * AST * sizeof(float);  // 104,448 B
    cudaFuncSetAttribute(flash_tc_kernel,
                         cudaFuncAttributeMaxDynamicSharedMemorySize, smem);
    flash_tc_kernel<<<dim3(T_ / 128, H_, B_), 256, smem>>>(q, k, v, mask, ctx);

    gemm_tc_kernel<<<ggrid, 256>>>(ctx, Wo, bo, (float*)d_out, M_, D_, D_);
}